// round 4
// baseline (speedup 1.0000x reference)
#include <cuda_runtime.h>
#include <math.h>

typedef unsigned long long ull;

// ---------------- problem constants ----------------
constexpr int CH   = 120;
constexpr int NWIN = 1024;          // total windows (4 * 4 * 8 * 8)
constexpr int NTOK = NWIN * 128;    // 131072
constexpr float SCALE_F = 0.22360679774997896f;  // 20^-0.5

// ---------------- scratch ----------------
__device__ float g_xw   [(size_t)NTOK * CH];    // LN1'd, rolled, windowed
__device__ float g_qkv_s[(size_t)NTOK * 360];   // layout [win][360][128]
__device__ float g_qkv_m[(size_t)NTOK * 360];   // layout [win][360][128]
__device__ float g_xout [(size_t)NTOK * 240];   // layout [win][240][128]
__device__ float g_xres [(size_t)NTOK * CH];    // x + attn branch (plain layout)
__device__ float g_z    [(size_t)NTOK * CH];    // LN2 output
__device__ float g_h    [(size_t)NTOK * 480];   // fc11|fc12 pre-activations

// ---------------- f32x2 helpers ----------------
__device__ __forceinline__ void fma2(ull& d, ull a, ull b) {
    asm("fma.rn.f32x2 %0, %1, %2, %0;" : "+l"(d) : "l"(a), "l"(b));
}
__device__ __forceinline__ ull pack2(float lo, float hi) {
    ull r; asm("mov.b64 %0, {%1, %2};" : "=l"(r) : "f"(lo), "f"(hi)); return r;
}
__device__ __forceinline__ float2 u2f(ull v) {
    float2 f; asm("mov.b64 {%0, %1}, %2;" : "=f"(f.x), "=f"(f.y) : "l"(v)); return f;
}

__device__ __forceinline__ float gelu_exact(float v) {
    return 0.5f * v * (1.0f + erff(v * 0.70710678118654752f));
}

// token (wi,t) -> rolled source/dest offset in (B,D,H,W,C) layout
__device__ __forceinline__ size_t roll_offset(int wi, int t) {
    int wB = wi & 7, hB = (wi >> 3) & 7, dB = (wi >> 6) & 3, bb = wi >> 8;
    int dt = t >> 6, ht = (t >> 3) & 7, wt = t & 7;
    int ds = (dB * 2 + dt + 1) & 7;
    int hs = (hB * 8 + ht + 4) & 63;
    int ws = (wB * 8 + wt + 4) & 63;
    return (size_t)((((bb * 8 + ds) * 64 + hs) * 64 + ws)) * CH;
}

// ---------------- K1: LN1 + roll + window partition ----------------
__global__ void k_ln1(const float* __restrict__ x, const float* __restrict__ g,
                      const float* __restrict__ b) {
    int warp = (blockIdx.x * blockDim.x + threadIdx.x) >> 5;
    int lane = threadIdx.x & 31;
    if (warp >= NTOK) return;
    int wi = warp >> 7, t = warp & 127;
    const float* src = x + roll_offset(wi, t);
    float v0 = 0, v1 = 0, v2 = 0, v3 = 0, s = 0, sq = 0;
    if (lane < 30) {
        float4 f = *(const float4*)(src + lane * 4);
        v0 = f.x; v1 = f.y; v2 = f.z; v3 = f.w;
        s  = v0 + v1 + v2 + v3;
        sq = v0 * v0 + v1 * v1 + v2 * v2 + v3 * v3;
    }
#pragma unroll
    for (int o = 16; o; o >>= 1) {
        s  += __shfl_xor_sync(0xffffffffu, s, o);
        sq += __shfl_xor_sync(0xffffffffu, sq, o);
    }
    float mean = s * (1.0f / 120.0f);
    float var  = sq * (1.0f / 120.0f) - mean * mean;
    float r = rsqrtf(var + 1e-5f);
    if (lane < 30) {
        int c = lane * 4;
        float* dst = g_xw + (size_t)warp * CH + c;
        dst[0] = (v0 - mean) * r * g[c]     + b[c];
        dst[1] = (v1 - mean) * r * g[c + 1] + b[c + 1];
        dst[2] = (v2 - mean) * r * g[c + 2] + b[c + 2];
        dst[3] = (v3 - mean) * r * g[c + 3] + b[c + 3];
    }
}

// ---------------- LN2 (plain layout) ----------------
__global__ void k_ln2(const float* __restrict__ g, const float* __restrict__ b) {
    int warp = (blockIdx.x * blockDim.x + threadIdx.x) >> 5;
    int lane = threadIdx.x & 31;
    if (warp >= NTOK) return;
    const float* src = g_xres + (size_t)warp * CH;
    float v0 = 0, v1 = 0, v2 = 0, v3 = 0, s = 0, sq = 0;
    if (lane < 30) {
        float4 f = *(const float4*)(src + lane * 4);
        v0 = f.x; v1 = f.y; v2 = f.z; v3 = f.w;
        s  = v0 + v1 + v2 + v3;
        sq = v0 * v0 + v1 * v1 + v2 * v2 + v3 * v3;
    }
#pragma unroll
    for (int o = 16; o; o >>= 1) {
        s  += __shfl_xor_sync(0xffffffffu, s, o);
        sq += __shfl_xor_sync(0xffffffffu, sq, o);
    }
    float mean = s * (1.0f / 120.0f);
    float var  = sq * (1.0f / 120.0f) - mean * mean;
    float r = rsqrtf(var + 1e-5f);
    if (lane < 30) {
        int c = lane * 4;
        float* dst = g_z + (size_t)warp * CH + c;
        dst[0] = (v0 - mean) * r * g[c]     + b[c];
        dst[1] = (v1 - mean) * r * g[c + 1] + b[c + 1];
        dst[2] = (v2 - mean) * r * g[c + 2] + b[c + 2];
        dst[3] = (v3 - mean) * r * g[c + 3] + b[c + 3];
    }
}

// ---------------- generic SGEMM: out = A @ B^T + epilogue ----------------
// MODE 0: qkv self (A=g_xw, K=120, N=360, out [win][n][128] via smem transpose)
// MODE 1: qkv mut  (A=g_xw + pos(extra), rest same as MODE 0)
// MODE 2: proj     (A=g_xout [win][240][128], K=240, N=120,
//                   epi: scatter(roll) + x(extra) add -> g_xres row-major)
// MODE 3: mlp1     (B split fc11/fc12, K=120, N=480, out row-major)
// MODE 4: mlp2     (A = gelu-gate from g_h (phys 480), K=240, N=120,
//                   epi: + g_xres(extra) -> d_out row-major)
template <int KD, int MODE>
__global__ void __launch_bounds__(256) k_gemm(
    const float* __restrict__ A, const float* __restrict__ B1,
    const float* __restrict__ B2, const float* __restrict__ bias,
    const float* __restrict__ bias2, const float* __restrict__ extra,
    float* __restrict__ out, int Ntot) {
    __shared__ float smem_all[2048];
    float* As = smem_all;          // [8][128]
    float* Bs = smem_all + 1024;   // [8][128]
    int tid = threadIdx.x;
    int m0 = blockIdx.x * 128;
    int n0 = blockIdx.y * 128;
    int tx = tid & 15, ty = tid >> 4;
    int lr = tid >> 1;          // load row 0..127
    int lc = (tid & 1) * 4;     // load col offset (0 or 4)
    int win = m0 >> 7;

    ull acc2[2][2][2][4];       // [gi][ipair][gj][j]
#pragma unroll
    for (int a = 0; a < 2; a++)
#pragma unroll
        for (int p = 0; p < 2; p++)
#pragma unroll
            for (int g = 0; g < 2; g++)
#pragma unroll
                for (int j = 0; j < 4; j++) acc2[a][p][g][j] = 0ULL;

    int am = m0 + lr;
    int bn = n0 + lr;
    bool bvalid = bn < Ntot;
    const float* bsrc;
    if (MODE == 3) {
        bsrc = (bn < 240) ? (B1 + (size_t)bn * KD)
                          : (B2 + (size_t)(bn - 240) * KD);
    } else {
        bsrc = B1 + (size_t)(bvalid ? bn : 0) * KD;
    }

    for (int k0 = 0; k0 < KD; k0 += 8) {
        float4 av;
        if (MODE == 2) {
            // A in [win][240][128]: cooperative coalesced tile load
            int kk = tid >> 5;
            int mc = (tid & 31) * 4;
            av = *(const float4*)(A + ((size_t)win * 240 + k0 + kk) * 128 + mc);
        } else if (MODE == 4) {
            const float* hp = A + (size_t)am * 480 + k0 + lc;
            float4 h1 = *(const float4*)hp;
            float4 h2 = *(const float4*)(hp + 240);
            av.x = gelu_exact(h1.x) * h2.x;
            av.y = gelu_exact(h1.y) * h2.y;
            av.z = gelu_exact(h1.z) * h2.z;
            av.w = gelu_exact(h1.w) * h2.w;
        } else {
            av = *(const float4*)(A + (size_t)am * KD + k0 + lc);
            if (MODE == 1) {
                int tt = am & 63;
                float4 p = *(const float4*)(extra + (size_t)tt * CH + k0 + lc);
                av.x += p.x; av.y += p.y; av.z += p.z; av.w += p.w;
            }
        }
        float4 bv = make_float4(0.f, 0.f, 0.f, 0.f);
        if (bvalid) bv = *(const float4*)(bsrc + k0 + lc);

        __syncthreads();
        if (MODE == 2) {
            int kk = tid >> 5;
            int mc = (tid & 31) * 4;
            *(float4*)&As[kk * 128 + mc] = av;
        } else {
            As[(lc + 0) * 128 + lr] = av.x; As[(lc + 1) * 128 + lr] = av.y;
            As[(lc + 2) * 128 + lr] = av.z; As[(lc + 3) * 128 + lr] = av.w;
        }
        Bs[(lc + 0) * 128 + lr] = bv.x; Bs[(lc + 1) * 128 + lr] = bv.y;
        Bs[(lc + 2) * 128 + lr] = bv.z; Bs[(lc + 3) * 128 + lr] = bv.w;
        __syncthreads();

#pragma unroll
        for (int kk = 0; kk < 8; kk++) {
            ull a00 = *(const ull*)&As[kk * 128 + ty * 4];
            ull a01 = *(const ull*)&As[kk * 128 + ty * 4 + 2];
            ull a10 = *(const ull*)&As[kk * 128 + 64 + ty * 4];
            ull a11 = *(const ull*)&As[kk * 128 + 64 + ty * 4 + 2];
            float4 b0 = *(const float4*)&Bs[kk * 128 + tx * 4];
            float4 b1 = *(const float4*)&Bs[kk * 128 + 64 + tx * 4];
            ull bd[2][4];
            bd[0][0] = pack2(b0.x, b0.x); bd[0][1] = pack2(b0.y, b0.y);
            bd[0][2] = pack2(b0.z, b0.z); bd[0][3] = pack2(b0.w, b0.w);
            bd[1][0] = pack2(b1.x, b1.x); bd[1][1] = pack2(b1.y, b1.y);
            bd[1][2] = pack2(b1.z, b1.z); bd[1][3] = pack2(b1.w, b1.w);
#pragma unroll
            for (int gj = 0; gj < 2; gj++)
#pragma unroll
                for (int j = 0; j < 4; j++) {
                    fma2(acc2[0][0][gj][j], a00, bd[gj][j]);
                    fma2(acc2[0][1][gj][j], a01, bd[gj][j]);
                    fma2(acc2[1][0][gj][j], a10, bd[gj][j]);
                    fma2(acc2[1][1][gj][j], a11, bd[gj][j]);
                }
        }
    }

    if (MODE == 0 || MODE == 1) {
        // transposed coalesced epilogue: out tile [n0..n0+127][128] of window `win`
        __syncthreads();
        int nrow = tid >> 4;            // 0..15
        int mcol = (tid & 15) * 8;
#pragma unroll 1
        for (int c = 0; c < 8; c++) {
            int gj = c >> 2;
            if ((tx >> 2) == (c & 3)) {
#pragma unroll
                for (int j = 0; j < 4; j++) {
                    int nl = gj * 64 + tx * 4 + j;
                    int nr = nl & 15;
#pragma unroll
                    for (int gi = 0; gi < 2; gi++)
#pragma unroll
                        for (int ip = 0; ip < 2; ip++) {
                            float2 f = u2f(acc2[gi][ip][gj][j]);
                            smem_all[nr * 128 + gi * 64 + ty * 4 + ip * 2]     = f.x;
                            smem_all[nr * 128 + gi * 64 + ty * 4 + ip * 2 + 1] = f.y;
                        }
                }
            }
            __syncthreads();
            int n = n0 + c * 16 + nrow;
            if (n < Ntot) {
                float bz = bias[n];
                float4 x1 = *(float4*)&smem_all[nrow * 128 + mcol];
                float4 x2 = *(float4*)&smem_all[nrow * 128 + mcol + 4];
                x1.x += bz; x1.y += bz; x1.z += bz; x1.w += bz;
                x2.x += bz; x2.y += bz; x2.z += bz; x2.w += bz;
                float* op = out + ((size_t)win * 360 + n) * 128 + mcol;
                *(float4*)op = x1;
                *(float4*)(op + 4) = x2;
            }
            __syncthreads();
        }
        return;
    }

    // scalar epilogues (MODE 2/3/4)
#pragma unroll
    for (int gi = 0; gi < 2; gi++)
#pragma unroll
        for (int i = 0; i < 4; i++) {
            int m = m0 + gi * 64 + ty * 4 + i;
            size_t drow;
            if (MODE == 2) {
                drow = roll_offset(m >> 7, m & 127);
            } else {
                drow = (size_t)m * Ntot;
            }
#pragma unroll
            for (int gj = 0; gj < 2; gj++)
#pragma unroll
                for (int j = 0; j < 4; j++) {
                    int n = n0 + gj * 64 + tx * 4 + j;
                    if (n >= Ntot) continue;
                    float2 f = u2f(acc2[gi][i >> 1][gj][j]);
                    float v = (i & 1) ? f.y : f.x;
                    if (MODE == 2) {
                        v += bias[n] + extra[drow + n];
                    } else if (MODE == 3) {
                        v += (n < 240) ? bias[n] : bias2[n - 240];
                    } else {  // MODE 4
                        v += bias[n] + extra[(size_t)m * 120 + n];
                    }
                    out[drow + n] = v;
                }
        }
}

// ---------------- K4: attention (self + mutual), block = (window, head) ----
__global__ void __launch_bounds__(128) k_attn(const float* __restrict__ rpb) {
    __shared__ float sk[128 * 24];
    __shared__ float sv[128 * 24];
    __shared__ float srpb[675];
    __shared__ int   sg[128];

    int wi = blockIdx.x, h = blockIdx.y;
    int t = threadIdx.x;

    for (int i = t; i < 675; i += 128) srpb[i] = rpb[i * 6 + h];

    // token / window coordinates
    int dt = t >> 6, ht = (t >> 3) & 7, wt = t & 7;
    int dB = (wi >> 6) & 3, hB = (wi >> 3) & 7, wB = wi & 7;
    int dd = dB * 2 + dt, hh = hB * 8 + ht, ww = wB * 8 + wt;
    int gd = (dd < 6) ? 0 : ((dd < 7) ? 1 : 2);
    int gh = (hh < 56) ? 0 : ((hh < 60) ? 1 : 2);
    int gw = (ww < 56) ? 0 : ((ww < 60) ? 1 : 2);
    int grp = gd * 9 + gh * 3 + gw;
    int gd0 = (dB * 2 < 6) ? 0 : 1;
    int grp0 = gd0 * 9 + gh * 3 + gw;
    int ccode = dt * 225 + ht * 15 + wt;
    sg[t] = ccode | (grp << 10) | (grp0 << 16);
    int rbase = (dt + 1) * 225 + (ht + 7) * 15 + (wt + 7);

    // ---- self QKV load (coalesced) ----
    const float* Q = g_qkv_s + (size_t)wi * 360 * 128;
    ull q2[10];
#pragma unroll
    for (int d = 0; d < 10; d++) {
        float lo = Q[(h * 20 + 2 * d) * 128 + t] * SCALE_F;
        float hi = Q[(h * 20 + 2 * d + 1) * 128 + t] * SCALE_F;
        q2[d] = pack2(lo, hi);
    }
#pragma unroll
    for (int d = 0; d < 20; d++) {
        sk[t * 24 + d] = Q[(120 + h * 20 + d) * 128 + t];
        sv[t * 24 + d] = Q[(240 + h * 20 + d) * 128 + t];
    }
    __syncthreads();

    ull o2[10];
#pragma unroll
    for (int d = 0; d < 10; d++) o2[d] = 0ULL;
    float sum = 0.f;

#pragma unroll 2
    for (int m = 0; m < 128; m++) {
        int s = sg[m];
        const ulonglong2* kr = (const ulonglong2*)(sk + m * 24);
        ulonglong2 k0 = kr[0], k1 = kr[1], k2 = kr[2], k3 = kr[3], k4 = kr[4];
        ull aA = 0ULL, aB = 0ULL;
        fma2(aA, q2[0], k0.x); fma2(aB, q2[1], k0.y);
        fma2(aA, q2[2], k1.x); fma2(aB, q2[3], k1.y);
        fma2(aA, q2[4], k2.x); fma2(aB, q2[5], k2.y);
        fma2(aA, q2[6], k3.x); fma2(aB, q2[7], k3.y);
        fma2(aA, q2[8], k4.x); fma2(aB, q2[9], k4.y);
        float2 fa = u2f(aA), fb = u2f(aB);
        float logit = (fa.x + fa.y) + (fb.x + fb.y) + srpb[rbase - (s & 1023)];
        float p = (((s >> 10) & 31) == grp) ? __expf(logit) : 0.f;
        sum += p;
        ull pd = pack2(p, p);
        const ulonglong2* vr = (const ulonglong2*)(sv + m * 24);
        ulonglong2 v0 = vr[0], v1 = vr[1], v2 = vr[2], v3 = vr[3], v4 = vr[4];
        fma2(o2[0], pd, v0.x); fma2(o2[1], pd, v0.y);
        fma2(o2[2], pd, v1.x); fma2(o2[3], pd, v1.y);
        fma2(o2[4], pd, v2.x); fma2(o2[5], pd, v2.y);
        fma2(o2[6], pd, v3.x); fma2(o2[7], pd, v3.y);
        fma2(o2[8], pd, v4.x); fma2(o2[9], pd, v4.y);
    }
    {
        float inv = 1.0f / sum;
        float* ob = g_xout + ((size_t)wi * 240 + 120 + h * 20) * 128 + t;
#pragma unroll
        for (int d = 0; d < 10; d++) {
            float2 f = u2f(o2[d]);
            ob[(2 * d) * 128]     = f.x * inv;
            ob[(2 * d + 1) * 128] = f.y * inv;
        }
    }
    __syncthreads();  // done with sk/sv before overwrite

    // ---- mutual attention ----
    int qrow = t ^ 64;
    int mb   = (t < 64) ? 0 : 64;
    const float* Qm = g_qkv_m + (size_t)wi * 360 * 128;
#pragma unroll
    for (int d = 0; d < 20; d++) {
        sk[t * 24 + d] = Qm[(120 + h * 20 + d) * 128 + t];
        sv[t * 24 + d] = Qm[(240 + h * 20 + d) * 128 + t];
    }
#pragma unroll
    for (int d = 0; d < 10; d++) {
        float lo = Qm[(h * 20 + 2 * d) * 128 + qrow] * SCALE_F;
        float hi = Qm[(h * 20 + 2 * d + 1) * 128 + qrow] * SCALE_F;
        q2[d] = pack2(lo, hi);
    }
    __syncthreads();

#pragma unroll
    for (int d = 0; d < 10; d++) o2[d] = 0ULL;
    sum = 0.f;
    int mygrp0 = (sg[t & 63] >> 16) & 31;

#pragma unroll 2
    for (int m = 0; m < 64; m++) {
        int s = sg[m];
        const ulonglong2* kr = (const ulonglong2*)(sk + (mb + m) * 24);
        ulonglong2 k0 = kr[0], k1 = kr[1], k2 = kr[2], k3 = kr[3], k4 = kr[4];
        ull aA = 0ULL, aB = 0ULL;
        fma2(aA, q2[0], k0.x); fma2(aB, q2[1], k0.y);
        fma2(aA, q2[2], k1.x); fma2(aB, q2[3], k1.y);
        fma2(aA, q2[4], k2.x); fma2(aB, q2[5], k2.y);
        fma2(aA, q2[6], k3.x); fma2(aB, q2[7], k3.y);
        fma2(aA, q2[8], k4.x); fma2(aB, q2[9], k4.y);
        float2 fa = u2f(aA), fb = u2f(aB);
        float logit = (fa.x + fa.y) + (fb.x + fb.y);
        float p = (((s >> 16) & 31) == mygrp0) ? __expf(logit) : 0.f;
        sum += p;
        ull pd = pack2(p, p);
        const ulonglong2* vr = (const ulonglong2*)(sv + (mb + m) * 24);
        ulonglong2 v0 = vr[0], v1 = vr[1], v2 = vr[2], v3 = vr[3], v4 = vr[4];
        fma2(o2[0], pd, v0.x); fma2(o2[1], pd, v0.y);
        fma2(o2[2], pd, v1.x); fma2(o2[3], pd, v1.y);
        fma2(o2[4], pd, v2.x); fma2(o2[5], pd, v2.y);
        fma2(o2[6], pd, v3.x); fma2(o2[7], pd, v3.y);
        fma2(o2[8], pd, v4.x); fma2(o2[9], pd, v4.y);
    }
    {
        float inv = 1.0f / sum;
        float* ob = g_xout + ((size_t)wi * 240 + h * 20) * 128 + t;
#pragma unroll
        for (int d = 0; d < 10; d++) {
            float2 f = u2f(o2[d]);
            ob[(2 * d) * 128]     = f.x * inv;
            ob[(2 * d + 1) * 128] = f.y * inv;
        }
    }
}

// ---------------- launch ----------------
extern "C" void kernel_launch(void* const* d_in, const int* in_sizes, int n_in,
                              void* d_out, int out_size) {
    const float* x          = (const float*)d_in[0];
    const float* g1         = (const float*)d_in[2];
    const float* b1         = (const float*)d_in[3];
    const float* qkv_self_w = (const float*)d_in[4];
    const float* qkv_self_b = (const float*)d_in[5];
    const float* qkv_mut_w  = (const float*)d_in[6];
    const float* qkv_mut_b  = (const float*)d_in[7];
    const float* proj_w     = (const float*)d_in[8];
    const float* proj_b     = (const float*)d_in[9];
    const float* rpb        = (const float*)d_in[10];
    const float* pos        = (const float*)d_in[11];
    const float* g2         = (const float*)d_in[12];
    const float* b2         = (const float*)d_in[13];
    const float* fc11_w     = (const float*)d_in[14];
    const float* fc11_b     = (const float*)d_in[15];
    const float* fc12_w     = (const float*)d_in[16];
    const float* fc12_b     = (const float*)d_in[17];
    const float* fc2_w      = (const float*)d_in[18];
    const float* fc2_b      = (const float*)d_in[19];
    float* out = (float*)d_out;

    float* xw   = nullptr; cudaGetSymbolAddress((void**)&xw,   g_xw);
    float* qkvs = nullptr; cudaGetSymbolAddress((void**)&qkvs, g_qkv_s);
    float* qkvm = nullptr; cudaGetSymbolAddress((void**)&qkvm, g_qkv_m);
    float* xo   = nullptr; cudaGetSymbolAddress((void**)&xo,   g_xout);
    float* xres = nullptr; cudaGetSymbolAddress((void**)&xres, g_xres);
    float* zb   = nullptr; cudaGetSymbolAddress((void**)&zb,   g_z);
    float* hb   = nullptr; cudaGetSymbolAddress((void**)&hb,   g_h);

    // 1. LN1 + roll + window partition
    k_ln1<<<NTOK / 8, 256>>>(x, g1, b1);
    // 2. QKV self (-> [win][360][128])
    k_gemm<120, 0><<<dim3(NTOK / 128, 3), 256>>>(
        xw, qkv_self_w, nullptr, qkv_self_b, nullptr, nullptr, qkvs, 360);
    // 3. QKV mutual (+ pos bias on A, -> [win][360][128])
    k_gemm<120, 1><<<dim3(NTOK / 128, 3), 256>>>(
        xw, qkv_mut_w, nullptr, qkv_mut_b, nullptr, pos, qkvm, 360);
    // 4. attention (-> g_xout [win][240][128])
    k_attn<<<dim3(NWIN, 6), 128>>>(rpb);
    // 5. proj + window-reverse + roll-back + shortcut add
    k_gemm<240, 2><<<dim3(NTOK / 128, 1), 256>>>(
        xo, proj_w, nullptr, proj_b, nullptr, x, xres, 120);
    // 6. LN2
    k_ln2<<<NTOK / 8, 256>>>(g2, b2);
    // 7. fc11 | fc12
    k_gemm<120, 3><<<dim3(NTOK / 128, 4), 256>>>(
        zb, fc11_w, fc12_w, fc11_b, fc12_b, nullptr, hb, 480);
    // 8. gelu-gate + fc2 + residual -> out
    k_gemm<240, 4><<<dim3(NTOK / 128, 1), 256>>>(
        hb, fc2_w, nullptr, fc2_b, nullptr, xres, out, 120);
}